// round 1
// baseline (speedup 1.0000x reference)
#include <cuda_runtime.h>
#include <stdint.h>

// Bidirectional chamfer distance, B=4, N=M=5000, D=3.
// d2/2 = hx + hy - x.y with hx=0.5|x|^2. Per thread: 2 queries packed in f32x2
// halves; ref broadcast from SMEM stored duplicated {x,x,y,y,z,z,h,h} so
// ld.shared.v2.u64 yields aligned 64-bit f32x2 operands directly.

#define B_    4
#define N_    5000
#define S_    8          // ref split (split-K over refs)
#define CHUNK 625        // N_/S_
#define TPB   128        // threads per block
#define QPB   256        // queries per block (2 per thread)
#define QB    20         // ceil(5000/256)
#define RPAD  640        // padded refs per chunk (multiple of unroll)
#define NBLK_B 40
#define TPB_B  256

// Scratch (no allocation allowed): partial mins per (dir,b,q,s), block sums.
__device__ __align__(16) float g_part[2 * B_ * N_ * S_];   // 320000 floats
__device__ float g_bsums[NBLK_B];

__global__ __launch_bounds__(TPB) void chamfer_main(const float* __restrict__ pred,
                                                    const float* __restrict__ gt) {
    __shared__ __align__(32) float smf[RPAD * 8];   // 20480 B

    const int qb  = blockIdx.x;          // query block 0..QB-1
    const int bd  = blockIdx.y;          // dir*B_ + b, 0..7
    const int s   = blockIdx.z;          // ref split 0..S_-1
    const int dir = bd >> 2;             // 0: pred->gt, 1: gt->pred
    const int b   = bd & 3;

    const float* __restrict__ qbase = (dir == 0 ? pred : gt) + b * N_ * 3;
    const float* __restrict__ rbase = (dir == 0 ? gt : pred) + b * N_ * 3 + s * CHUNK * 3;

    const int tid = threadIdx.x;

    // Cooperative load of the ref chunk, duplicated per-point for f32x2 ops.
    for (int r = tid; r < RPAD; r += TPB) {
        float gx, gy, gz, h;
        if (r < CHUNK) {
            gx = rbase[r * 3 + 0];
            gy = rbase[r * 3 + 1];
            gz = rbase[r * 3 + 2];
            h  = 0.5f * (gx * gx + gy * gy + gz * gz);
        } else {
            gx = 0.0f; gy = 0.0f; gz = 0.0f; h = 1.0e30f;  // sentinel: never the min
        }
        smf[r * 8 + 0] = gx; smf[r * 8 + 1] = gx;
        smf[r * 8 + 2] = gy; smf[r * 8 + 3] = gy;
        smf[r * 8 + 4] = gz; smf[r * 8 + 5] = gz;
        smf[r * 8 + 6] = h;  smf[r * 8 + 7] = h;
    }

    // Two queries per thread (clamped; out-of-range ones are not written back).
    const int q0 = qb * QPB + tid;
    const int q1 = q0 + TPB;
    const int q0c = q0 < N_ ? q0 : N_ - 1;
    const int q1c = q1 < N_ ? q1 : N_ - 1;
    const float ax = qbase[q0c * 3 + 0], ay = qbase[q0c * 3 + 1], az = qbase[q0c * 3 + 2];
    const float bx = qbase[q1c * 3 + 0], by = qbase[q1c * 3 + 1], bz = qbase[q1c * 3 + 2];
    const float h0 = 0.5f * (ax * ax + ay * ay + az * az);
    const float h1 = 0.5f * (bx * bx + by * by + bz * bz);

    // Packed negated query coords: lo half = query0, hi half = query1.
    uint64_t nx2, ny2, nz2;
    asm("mov.b64 %0, {%1, %2};" : "=l"(nx2) : "f"(-ax), "f"(-bx));
    asm("mov.b64 %0, {%1, %2};" : "=l"(ny2) : "f"(-ay), "f"(-by));
    asm("mov.b64 %0, {%1, %2};" : "=l"(nz2) : "f"(-az), "f"(-bz));

    __syncthreads();

    uint32_t sbase = (uint32_t)__cvta_generic_to_shared(smf);

    float m0 = 1.0e30f, m1 = 1.0e30f;
#pragma unroll 4
    for (int p = 0; p < RPAD; ++p) {
        uint64_t rx, ry, rz, rh;
        uint32_t a = sbase + p * 32;
        asm("ld.shared.v2.u64 {%0, %1}, [%2];" : "=l"(rx), "=l"(ry) : "r"(a));
        asm("ld.shared.v2.u64 {%0, %1}, [%2];" : "=l"(rz), "=l"(rh) : "r"(a + 16));
        float u0, u1;
        // u = h - q.r  (for both packed queries), 3x fma.rn.f32x2
        asm("{\n\t"
            ".reg .b64 t;\n\t"
            "fma.rn.f32x2 t, %2, %3, %4;\n\t"
            "fma.rn.f32x2 t, %5, %6, t;\n\t"
            "fma.rn.f32x2 t, %7, %8, t;\n\t"
            "mov.b64 {%0, %1}, t;\n\t"
            "}"
            : "=f"(u0), "=f"(u1)
            : "l"(nz2), "l"(rz), "l"(rh),
              "l"(ny2), "l"(ry),
              "l"(nx2), "l"(rx));
        m0 = fminf(m0, u0);
        m1 = fminf(m1, u1);
    }

    // Partial (unclamped) d2 for this ref chunk; min over s and clamp later.
    const int base = (dir * B_ + b) * N_;
    if (q0 < N_) g_part[(base + q0) * S_ + s] = 2.0f * (h0 + m0);
    if (q1 < N_) g_part[(base + q1) * S_ + s] = 2.0f * (h1 + m1);
}

__global__ __launch_bounds__(TPB_B) void chamfer_reduce1() {
    __shared__ float ssum[TPB_B];
    const int gtid = blockIdx.x * TPB_B + threadIdx.x;
    float acc = 0.0f;
    for (int q = gtid; q < 2 * B_ * N_; q += NBLK_B * TPB_B) {
        const float4* p4 = (const float4*)(g_part + q * S_);
        float4 a = p4[0];
        float4 c = p4[1];
        float m = fminf(fminf(fminf(a.x, a.y), fminf(a.z, a.w)),
                        fminf(fminf(c.x, c.y), fminf(c.z, c.w)));
        acc += fmaxf(m, 0.0f);
    }
    ssum[threadIdx.x] = acc;
    __syncthreads();
    for (int off = TPB_B / 2; off > 0; off >>= 1) {
        if (threadIdx.x < off) ssum[threadIdx.x] += ssum[threadIdx.x + off];
        __syncthreads();
    }
    if (threadIdx.x == 0) g_bsums[blockIdx.x] = ssum[0];
}

__global__ void chamfer_reduce2(float* __restrict__ out) {
    __shared__ float sv[64];
    float v = (threadIdx.x < NBLK_B) ? g_bsums[threadIdx.x] : 0.0f;
    sv[threadIdx.x] = v;
    __syncthreads();
    if (threadIdx.x == 0) {
        float t = 0.0f;
#pragma unroll
        for (int i = 0; i < 64; ++i) t += sv[i];
        // result = (sum_x + sum_y) / (B*N)   (N == M)
        out[0] = t * (1.0f / (B_ * N_));
    }
}

extern "C" void kernel_launch(void* const* d_in, const int* in_sizes, int n_in,
                              void* d_out, int out_size) {
    const float* pred = (const float*)d_in[0];
    const float* gt   = (const float*)d_in[1];
    dim3 grid(QB, 2 * B_, S_);
    chamfer_main<<<grid, TPB>>>(pred, gt);
    chamfer_reduce1<<<NBLK_B, TPB_B>>>();
    chamfer_reduce2<<<1, 64>>>((float*)d_out);
}

// round 3
// speedup vs baseline: 1.1688x; 1.1688x over previous
#include <cuda_runtime.h>
#include <stdint.h>

// Bidirectional chamfer distance, B=4, N=M=5000, D=3.
// d2/2 = hq + hr - q.r. 8 queries per thread as 4 f32x2 packed pairs;
// refs broadcast from SMEM duplicated {x,x,y,y,z,z,h,h} so ld.shared.v2.u64
// yields aligned 64-bit f32x2 operands. Packed fma.rn.f32x2; scalar FMNMX min
// (no min.f32x2 exists) on the unpacked result pair.

#define B_    4
#define N_    5000
#define S_    20         // ref split (split-K over refs)
#define CHUNK 250        // N_/S_
#define TPB   128        // threads per block
#define QPT   8          // queries per thread
#define QPB   1024       // queries per block
#define QB    5          // ceil(5000/1024)
#define RPAD  256        // padded refs per chunk (multiple of unroll)
#define NBLK_B 40
#define TPB_B  256

// Scratch: partial (unclamped) d2 per (dir,b,q,s), then block sums.
__device__ __align__(16) float g_part[2 * B_ * N_ * S_];   // 800000 floats
__device__ float g_bsums[NBLK_B];

__global__ __launch_bounds__(TPB) void chamfer_main(const float* __restrict__ pred,
                                                    const float* __restrict__ gt) {
    __shared__ __align__(32) float smf[RPAD * 8];   // 8 KB

    const int qb  = blockIdx.x;          // query block 0..QB-1
    const int bd  = blockIdx.y;          // dir*B_ + b, 0..7
    const int s   = blockIdx.z;          // ref split 0..S_-1
    const int dir = bd >> 2;             // 0: pred->gt, 1: gt->pred
    const int b   = bd & 3;

    const float* __restrict__ qbase = (dir == 0 ? pred : gt) + b * N_ * 3;
    const float* __restrict__ rbase = (dir == 0 ? gt : pred) + b * N_ * 3 + s * CHUNK * 3;

    const int tid = threadIdx.x;

    // Cooperative load of the ref chunk, duplicated per point for f32x2 ops.
    for (int r = tid; r < RPAD; r += TPB) {
        float gx, gy, gz, h;
        if (r < CHUNK) {
            gx = rbase[r * 3 + 0];
            gy = rbase[r * 3 + 1];
            gz = rbase[r * 3 + 2];
            h  = 0.5f * (gx * gx + gy * gy + gz * gz);
        } else {
            gx = 0.0f; gy = 0.0f; gz = 0.0f; h = 1.0e30f;  // sentinel
        }
        smf[r * 8 + 0] = gx; smf[r * 8 + 1] = gx;
        smf[r * 8 + 2] = gy; smf[r * 8 + 3] = gy;
        smf[r * 8 + 4] = gz; smf[r * 8 + 5] = gz;
        smf[r * 8 + 6] = h;  smf[r * 8 + 7] = h;
    }

    // 8 queries per thread: q_k = qb*QPB + tid + k*TPB, packed pairs (2j, 2j+1).
    int   qi[QPT];
    float hq[QPT];
    uint64_t nx2[4], ny2[4], nz2[4];
#pragma unroll
    for (int j = 0; j < 4; ++j) {
        int k0 = 2 * j, k1 = 2 * j + 1;
        int a = qb * QPB + tid + k0 * TPB;
        int c = qb * QPB + tid + k1 * TPB;
        qi[k0] = a; qi[k1] = c;
        int ac = a < N_ ? a : N_ - 1;
        int cc = c < N_ ? c : N_ - 1;
        float ax = qbase[ac * 3 + 0], ay = qbase[ac * 3 + 1], az = qbase[ac * 3 + 2];
        float bx = qbase[cc * 3 + 0], by = qbase[cc * 3 + 1], bz = qbase[cc * 3 + 2];
        hq[k0] = 0.5f * (ax * ax + ay * ay + az * az);
        hq[k1] = 0.5f * (bx * bx + by * by + bz * bz);
        asm("mov.b64 %0, {%1, %2};" : "=l"(nx2[j]) : "f"(-ax), "f"(-bx));
        asm("mov.b64 %0, {%1, %2};" : "=l"(ny2[j]) : "f"(-ay), "f"(-by));
        asm("mov.b64 %0, {%1, %2};" : "=l"(nz2[j]) : "f"(-az), "f"(-bz));
    }

    __syncthreads();

    uint32_t sbase = (uint32_t)__cvta_generic_to_shared(smf);

    float mn[QPT];
#pragma unroll
    for (int k = 0; k < QPT; ++k) mn[k] = 1.0e30f;

#pragma unroll 4
    for (int p = 0; p < RPAD; ++p) {
        uint64_t rx, ry, rz, rh;
        uint32_t a = sbase + p * 32;
        asm("ld.shared.v2.u64 {%0, %1}, [%2];" : "=l"(rx), "=l"(ry) : "r"(a));
        asm("ld.shared.v2.u64 {%0, %1}, [%2];" : "=l"(rz), "=l"(rh) : "r"(a + 16));
#pragma unroll
        for (int j = 0; j < 4; ++j) {
            // u = h - q.r for the two packed queries; unpack lands on the same
            // register pair the last FFMA2 wrote (mov elided by ptxas).
            float u0, u1;
            asm("{\n\t"
                ".reg .b64 t;\n\t"
                "fma.rn.f32x2 t, %2, %3, %4;\n\t"
                "fma.rn.f32x2 t, %5, %6, t;\n\t"
                "fma.rn.f32x2 t, %7, %8, t;\n\t"
                "mov.b64 {%0, %1}, t;\n\t"
                "}"
                : "=f"(u0), "=f"(u1)
                : "l"(nz2[j]), "l"(rz), "l"(rh),
                  "l"(ny2[j]), "l"(ry),
                  "l"(nx2[j]), "l"(rx));
            mn[2 * j]     = fminf(mn[2 * j], u0);
            mn[2 * j + 1] = fminf(mn[2 * j + 1], u1);
        }
    }

    // Write partial (unclamped) d2 for this ref chunk; min over s + clamp later.
    const int base = (dir * B_ + b) * N_;
#pragma unroll
    for (int k = 0; k < QPT; ++k) {
        if (qi[k] < N_) g_part[(base + qi[k]) * S_ + s] = 2.0f * (hq[k] + mn[k]);
    }
}

__global__ __launch_bounds__(TPB_B) void chamfer_reduce1() {
    __shared__ float ssum[TPB_B];
    const int gtid = blockIdx.x * TPB_B + threadIdx.x;
    float acc = 0.0f;
    for (int q = gtid; q < 2 * B_ * N_; q += NBLK_B * TPB_B) {
        const float4* p4 = (const float4*)(g_part + q * S_);
        float m = 1.0e30f;
#pragma unroll
        for (int i = 0; i < S_ / 4; ++i) {
            float4 a = p4[i];
            m = fminf(m, fminf(fminf(a.x, a.y), fminf(a.z, a.w)));
        }
        acc += fmaxf(m, 0.0f);
    }
    ssum[threadIdx.x] = acc;
    __syncthreads();
    for (int off = TPB_B / 2; off > 0; off >>= 1) {
        if (threadIdx.x < off) ssum[threadIdx.x] += ssum[threadIdx.x + off];
        __syncthreads();
    }
    if (threadIdx.x == 0) g_bsums[blockIdx.x] = ssum[0];
}

__global__ void chamfer_reduce2(float* __restrict__ out) {
    __shared__ float sv[64];
    float v = (threadIdx.x < NBLK_B) ? g_bsums[threadIdx.x] : 0.0f;
    sv[threadIdx.x] = v;
    __syncthreads();
    if (threadIdx.x == 0) {
        float t = 0.0f;
#pragma unroll
        for (int i = 0; i < 64; ++i) t += sv[i];
        out[0] = t * (1.0f / (B_ * N_));
    }
}

extern "C" void kernel_launch(void* const* d_in, const int* in_sizes, int n_in,
                              void* d_out, int out_size) {
    const float* pred = (const float*)d_in[0];
    const float* gt   = (const float*)d_in[1];
    dim3 grid(QB, 2 * B_, S_);
    chamfer_main<<<grid, TPB>>>(pred, gt);
    chamfer_reduce1<<<NBLK_B, TPB_B>>>();
    chamfer_reduce2<<<1, 64>>>((float*)d_out);
}

// round 4
// speedup vs baseline: 1.3348x; 1.1420x over previous
#include <cuda_runtime.h>
#include <stdint.h>

// Bidirectional chamfer distance, B=4, N=M=5000, D=3.
// d2/2 = hq + hr - q.r. 8 queries per thread as 4 f32x2 packed pairs;
// refs broadcast from SMEM duplicated {x,x,y,y,z,z,h,h} so ld.shared.v2.u64
// yields aligned 64-bit f32x2 operands. Packed fma.rn.f32x2; scalar FMNMX min.
// S=40 ref-split for occupancy (1600 blocks, ~10 CTAs/SM).

#define B_    4
#define N_    5000
#define S_    40         // ref split (split-K over refs)
#define CHUNK 125        // N_/S_
#define TPB   128        // threads per block
#define QPT   8          // queries per thread
#define QPB   1024       // queries per block
#define QB    5          // ceil(5000/1024)
#define RPAD  128        // padded refs per chunk (multiple of unroll)
#define NBLK_B 40
#define TPB_B  256

// Scratch: partial (unclamped) d2 per (dir,b,q,s), then block sums.
__device__ __align__(16) float g_part[2 * B_ * N_ * S_];   // 1.6M floats, 6.4MB
__device__ float g_bsums[NBLK_B];

__global__ __launch_bounds__(TPB) void chamfer_main(const float* __restrict__ pred,
                                                    const float* __restrict__ gt) {
    __shared__ __align__(32) float smf[RPAD * 8];   // 4 KB

    const int qb  = blockIdx.x;          // query block 0..QB-1
    const int bd  = blockIdx.y;          // dir*B_ + b, 0..7
    const int s   = blockIdx.z;          // ref split 0..S_-1
    const int dir = bd >> 2;             // 0: pred->gt, 1: gt->pred
    const int b   = bd & 3;

    const float* __restrict__ qbase = (dir == 0 ? pred : gt) + b * N_ * 3;
    const float* __restrict__ rbase = (dir == 0 ? gt : pred) + b * N_ * 3 + s * CHUNK * 3;

    const int tid = threadIdx.x;

    // Cooperative load of the ref chunk, duplicated per point for f32x2 ops.
    for (int r = tid; r < RPAD; r += TPB) {
        float gx, gy, gz, h;
        if (r < CHUNK) {
            gx = rbase[r * 3 + 0];
            gy = rbase[r * 3 + 1];
            gz = rbase[r * 3 + 2];
            h  = 0.5f * (gx * gx + gy * gy + gz * gz);
        } else {
            gx = 0.0f; gy = 0.0f; gz = 0.0f; h = 1.0e30f;  // sentinel
        }
        smf[r * 8 + 0] = gx; smf[r * 8 + 1] = gx;
        smf[r * 8 + 2] = gy; smf[r * 8 + 3] = gy;
        smf[r * 8 + 4] = gz; smf[r * 8 + 5] = gz;
        smf[r * 8 + 6] = h;  smf[r * 8 + 7] = h;
    }

    // 8 queries per thread: q_k = qb*QPB + tid + k*TPB, packed pairs (2j, 2j+1).
    int   qi[QPT];
    float hq[QPT];
    uint64_t nx2[4], ny2[4], nz2[4];
#pragma unroll
    for (int j = 0; j < 4; ++j) {
        int k0 = 2 * j, k1 = 2 * j + 1;
        int a = qb * QPB + tid + k0 * TPB;
        int c = qb * QPB + tid + k1 * TPB;
        qi[k0] = a; qi[k1] = c;
        int ac = a < N_ ? a : N_ - 1;
        int cc = c < N_ ? c : N_ - 1;
        float ax = qbase[ac * 3 + 0], ay = qbase[ac * 3 + 1], az = qbase[ac * 3 + 2];
        float bx = qbase[cc * 3 + 0], by = qbase[cc * 3 + 1], bz = qbase[cc * 3 + 2];
        hq[k0] = 0.5f * (ax * ax + ay * ay + az * az);
        hq[k1] = 0.5f * (bx * bx + by * by + bz * bz);
        asm("mov.b64 %0, {%1, %2};" : "=l"(nx2[j]) : "f"(-ax), "f"(-bx));
        asm("mov.b64 %0, {%1, %2};" : "=l"(ny2[j]) : "f"(-ay), "f"(-by));
        asm("mov.b64 %0, {%1, %2};" : "=l"(nz2[j]) : "f"(-az), "f"(-bz));
    }

    __syncthreads();

    uint32_t sbase = (uint32_t)__cvta_generic_to_shared(smf);

    float mn[QPT];
#pragma unroll
    for (int k = 0; k < QPT; ++k) mn[k] = 1.0e30f;

#pragma unroll 4
    for (int p = 0; p < RPAD; ++p) {
        uint64_t rx, ry, rz, rh;
        uint32_t a = sbase + p * 32;
        asm("ld.shared.v2.u64 {%0, %1}, [%2];" : "=l"(rx), "=l"(ry) : "r"(a));
        asm("ld.shared.v2.u64 {%0, %1}, [%2];" : "=l"(rz), "=l"(rh) : "r"(a + 16));
#pragma unroll
        for (int j = 0; j < 4; ++j) {
            // u = h - q.r for the two packed queries; unpack lands on the same
            // register pair the last FFMA2 wrote (mov elided by ptxas).
            float u0, u1;
            asm("{\n\t"
                ".reg .b64 t;\n\t"
                "fma.rn.f32x2 t, %2, %3, %4;\n\t"
                "fma.rn.f32x2 t, %5, %6, t;\n\t"
                "fma.rn.f32x2 t, %7, %8, t;\n\t"
                "mov.b64 {%0, %1}, t;\n\t"
                "}"
                : "=f"(u0), "=f"(u1)
                : "l"(nz2[j]), "l"(rz), "l"(rh),
                  "l"(ny2[j]), "l"(ry),
                  "l"(nx2[j]), "l"(rx));
            mn[2 * j]     = fminf(mn[2 * j], u0);
            mn[2 * j + 1] = fminf(mn[2 * j + 1], u1);
        }
    }

    // Write partial (unclamped) d2 for this ref chunk; min over s + clamp later.
    const int base = (dir * B_ + b) * N_;
#pragma unroll
    for (int k = 0; k < QPT; ++k) {
        if (qi[k] < N_) g_part[(base + qi[k]) * S_ + s] = 2.0f * (hq[k] + mn[k]);
    }
}

__global__ __launch_bounds__(TPB_B) void chamfer_reduce1() {
    __shared__ float ssum[TPB_B];
    const int gtid = blockIdx.x * TPB_B + threadIdx.x;
    float acc = 0.0f;
    for (int q = gtid; q < 2 * B_ * N_; q += NBLK_B * TPB_B) {
        const float4* p4 = (const float4*)(g_part + q * S_);
        float m = 1.0e30f;
#pragma unroll
        for (int i = 0; i < S_ / 4; ++i) {
            float4 a = p4[i];
            m = fminf(m, fminf(fminf(a.x, a.y), fminf(a.z, a.w)));
        }
        acc += fmaxf(m, 0.0f);
    }
    ssum[threadIdx.x] = acc;
    __syncthreads();
    for (int off = TPB_B / 2; off > 0; off >>= 1) {
        if (threadIdx.x < off) ssum[threadIdx.x] += ssum[threadIdx.x + off];
        __syncthreads();
    }
    if (threadIdx.x == 0) g_bsums[blockIdx.x] = ssum[0];
}

__global__ void chamfer_reduce2(float* __restrict__ out) {
    __shared__ float sv[64];
    float v = (threadIdx.x < NBLK_B) ? g_bsums[threadIdx.x] : 0.0f;
    sv[threadIdx.x] = v;
    __syncthreads();
    if (threadIdx.x == 0) {
        float t = 0.0f;
#pragma unroll
        for (int i = 0; i < 64; ++i) t += sv[i];
        out[0] = t * (1.0f / (B_ * N_));
    }
}

extern "C" void kernel_launch(void* const* d_in, const int* in_sizes, int n_in,
                              void* d_out, int out_size) {
    const float* pred = (const float*)d_in[0];
    const float* gt   = (const float*)d_in[1];
    dim3 grid(QB, 2 * B_, S_);
    chamfer_main<<<grid, TPB>>>(pred, gt);
    chamfer_reduce1<<<NBLK_B, TPB_B>>>();
    chamfer_reduce2<<<1, 64>>>((float*)d_out);
}